// round 2
// baseline (speedup 1.0000x reference)
#include <cuda_runtime.h>
#include <math.h>
#include <stdint.h>

// Problem dims
#define BB 128
#define TT 512
#define II 300
#define HH 256
#define G4 1024   // 4*H

// Scratch (device globals — no allocations allowed)
__device__ float g_xp[(size_t)TT * BB * G4];   // [t][b][gate]  (256 MB)
__device__ float g_h[2][BB * HH];              // ping-pong hidden state
__device__ float g_c[BB * HH];                 // cell state
__device__ float g_hb[BB * HH];                // backward-dir last hidden

__device__ __forceinline__ float sigmoidf(float v) {
    return 1.0f / (1.0f + expf(-v));
}

// ---------------------------------------------------------------------------
// Zero init of recurrent state (must be deterministic per launch/replay)
// ---------------------------------------------------------------------------
__global__ void init_state() {
    int i = blockIdx.x * blockDim.x + threadIdx.x;
    if (i < BB * HH) {
        g_h[0][i] = 0.0f;
        g_c[i] = 0.0f;
    }
}

// ---------------------------------------------------------------------------
// xp GEMM: xp[t][b][n] = sum_i x[b][t][i] * W_ih_f[n][i] + b_f[n]
// A: x as [M=65536][300] row-major (m = b*512 + t), B: W [1024][300]
// Tile 128x128, Ktile 8, 256 threads, 8x8 micro-tile.
// ---------------------------------------------------------------------------
__global__ void xp_gemm(const float* __restrict__ A,
                        const float* __restrict__ W,
                        const float* __restrict__ bias) {
    __shared__ float As[8][132];
    __shared__ float Bs[8][132];

    const int nt = blockIdx.x;          // 0..7
    const int mt = blockIdx.y;          // 0..511
    const int tid = threadIdx.x;        // 0..255
    const int tx = tid & 15;
    const int ty = tid >> 4;

    const int m0 = mt * 128;
    const int n0 = nt * 128;

    float acc[8][8];
#pragma unroll
    for (int i = 0; i < 8; i++)
#pragma unroll
        for (int j = 0; j < 8; j++) acc[i][j] = 0.0f;

    for (int k0 = 0; k0 < II; k0 += 8) {
#pragma unroll
        for (int e = tid; e < 1024; e += 256) {
            int r = e >> 3;
            int kk = e & 7;
            int k = k0 + kk;
            As[kk][r] = (k < II) ? A[(size_t)(m0 + r) * II + k] : 0.0f;
            Bs[kk][r] = (k < II) ? W[(size_t)(n0 + r) * II + k] : 0.0f;
        }
        __syncthreads();

#pragma unroll
        for (int kk = 0; kk < 8; kk++) {
            float a[8], b[8];
#pragma unroll
            for (int i = 0; i < 8; i++) a[i] = As[kk][ty * 8 + i];
#pragma unroll
            for (int j = 0; j < 8; j++) b[j] = Bs[kk][tx * 8 + j];
#pragma unroll
            for (int i = 0; i < 8; i++)
#pragma unroll
                for (int j = 0; j < 8; j++) acc[i][j] += a[i] * b[j];
        }
        __syncthreads();
    }

#pragma unroll
    for (int i = 0; i < 8; i++) {
        int m = m0 + ty * 8 + i;
        int bidx = m >> 9;      // m / 512
        int t = m & 511;        // m % 512
        size_t base = ((size_t)t * BB + bidx) * G4;
#pragma unroll
        for (int j = 0; j < 8; j++) {
            int n = n0 + tx * 8 + j;
            g_xp[base + n] = acc[i][j] + bias[n];
        }
    }
}

// ---------------------------------------------------------------------------
// Backward direction: only ONE step matters (h0=c0=0 on x[:, T-1]).
// g = x[b,T-1,:] @ W_ih_b^T + b_b ; c = sig(i)*tanh(g); h = sig(o)*tanh(c)
// One CTA per batch, warp-per-row dot products (coalesced W reads).
// ---------------------------------------------------------------------------
__global__ void bwd_last(const float* __restrict__ x,
                         const float* __restrict__ Wb,
                         const float* __restrict__ bb) {
    const int b = blockIdx.x;
    const int tid = threadIdx.x;        // 256
    __shared__ float xs[304];
    __shared__ float gs[G4];

    const float* xr = x + ((size_t)b * TT + (TT - 1)) * II;
    for (int i = tid; i < II; i += 256) xs[i] = xr[i];
    __syncthreads();

    const int wid = tid >> 5;
    const int lane = tid & 31;
    for (int r = wid; r < G4; r += 8) {
        float s = 0.0f;
        const float* wr = Wb + (size_t)r * II;
        for (int i = lane; i < II; i += 32) s += xs[i] * wr[i];
#pragma unroll
        for (int off = 16; off > 0; off >>= 1)
            s += __shfl_down_sync(0xffffffffu, s, off);
        if (lane == 0) gs[r] = s + bb[r];
    }
    __syncthreads();

    if (tid < HH) {
        float ig = sigmoidf(gs[tid]);
        float gg = tanhf(gs[512 + tid]);
        float og = sigmoidf(gs[768 + tid]);
        float c = ig * gg;               // f * c0 = 0
        g_hb[b * HH + tid] = og * tanhf(c);
    }
}

// ---------------------------------------------------------------------------
// One LSTM forward step.
// grid (kt=32, bt=4), 256 threads. CTA tile: 32 batches x 32 gate rows
// (= 8 hidden units x 4 gates). K=256 staged in two 128 chunks in smem.
// ---------------------------------------------------------------------------
__global__ void lstm_step(const float* __restrict__ Whh, int t, int parity) {
    __shared__ float sh_h[32][132];
    __shared__ float sh_w[32][132];
    __shared__ float sg[32][33];

    const float* __restrict__ h_in = g_h[parity];
    float* __restrict__ h_out = g_h[parity ^ 1];

    const int kt = blockIdx.x;           // 0..31 : hidden units kt*8 .. kt*8+7
    const int bt = blockIdx.y;           // 0..3  : batches bt*32 ..
    const int tid = threadIdx.x;
    const int tx = tid & 15;
    const int ty = tid >> 4;

    float a00 = 0.f, a01 = 0.f, a10 = 0.f, a11 = 0.f;

    for (int kc = 0; kc < HH; kc += 128) {
        // stage h tile: 32 batches x 128 k
#pragma unroll
        for (int v = tid; v < 32 * 32; v += 256) {
            int lb = v >> 5;
            int c4 = v & 31;
            float4 hv = *(const float4*)&h_in[(size_t)(bt * 32 + lb) * HH + kc + c4 * 4];
            *(float4*)&sh_h[lb][c4 * 4] = hv;
        }
        // stage W tile: 32 rows x 128 k. local row lr = g*8 + j -> global row g*256 + kt*8 + j
#pragma unroll
        for (int v = tid; v < 32 * 32; v += 256) {
            int lr = v >> 5;
            int c4 = v & 31;
            int grow = (lr >> 3) * HH + kt * 8 + (lr & 7);
            float4 wv = *(const float4*)&Whh[(size_t)grow * HH + kc + c4 * 4];
            *(float4*)&sh_w[lr][c4 * 4] = wv;
        }
        __syncthreads();

#pragma unroll
        for (int k4 = 0; k4 < 32; k4++) {
            float4 h0 = *(const float4*)&sh_h[ty][k4 * 4];
            float4 h1 = *(const float4*)&sh_h[ty + 16][k4 * 4];
            float4 w0 = *(const float4*)&sh_w[tx][k4 * 4];
            float4 w1 = *(const float4*)&sh_w[tx + 16][k4 * 4];
            a00 += h0.x * w0.x + h0.y * w0.y + h0.z * w0.z + h0.w * w0.w;
            a01 += h0.x * w1.x + h0.y * w1.y + h0.z * w1.z + h0.w * w1.w;
            a10 += h1.x * w0.x + h1.y * w0.y + h1.z * w0.z + h1.w * w0.w;
            a11 += h1.x * w1.x + h1.y * w1.y + h1.z * w1.z + h1.w * w1.w;
        }
        __syncthreads();
    }

    // add xp, stash preactivations so gates of one hidden unit meet in one thread
    {
        size_t xbase = ((size_t)t * BB + bt * 32) * G4;
        int lr0 = tx, lr1 = tx + 16;
        int grow0 = (lr0 >> 3) * HH + kt * 8 + (lr0 & 7);
        int grow1 = (lr1 >> 3) * HH + kt * 8 + (lr1 & 7);
        sg[ty][lr0]      = a00 + g_xp[xbase + (size_t)ty * G4 + grow0];
        sg[ty][lr1]      = a01 + g_xp[xbase + (size_t)ty * G4 + grow1];
        sg[ty + 16][lr0] = a10 + g_xp[xbase + (size_t)(ty + 16) * G4 + grow0];
        sg[ty + 16][lr1] = a11 + g_xp[xbase + (size_t)(ty + 16) * G4 + grow1];
    }
    __syncthreads();

    // gate update: 256 threads = 32 batches x 8 hidden units
    {
        int lb = tid >> 3;
        int j = tid & 7;
        float pi = sg[lb][j];        // i gate  (lr = 0*8 + j)
        float pf = sg[lb][8 + j];    // f gate
        float pg = sg[lb][16 + j];   // g gate
        float po = sg[lb][24 + j];   // o gate
        int b = bt * 32 + lb;
        int kh = kt * 8 + j;
        int idx = b * HH + kh;
        float ig = sigmoidf(pi);
        float fg = sigmoidf(pf);
        float gg = tanhf(pg);
        float og = sigmoidf(po);
        float c = fg * g_c[idx] + ig * gg;
        g_c[idx] = c;
        h_out[idx] = og * tanhf(c);
    }
}

// ---------------------------------------------------------------------------
// Final linear: out[b][j] = b_lin[j] + hf[b]·W_lin[j,0:256] + hb[b]·W_lin[j,256:512]
// hf lives in g_h[0] after 512 steps (parity: step t reads t&1, writes (t&1)^1).
// ---------------------------------------------------------------------------
__global__ void final_lin(const float* __restrict__ Wlin,
                          const float* __restrict__ blin,
                          float* __restrict__ out) {
    const int b = blockIdx.x;
    const int tid = threadIdx.x;  // 256
    __shared__ float s0[256];
    __shared__ float s1[256];

    float hf = g_h[0][b * HH + tid];
    float hb = g_hb[b * HH + tid];
    s0[tid] = hf * Wlin[tid] + hb * Wlin[HH + tid];
    s1[tid] = hf * Wlin[512 + tid] + hb * Wlin[512 + HH + tid];
    __syncthreads();
    for (int off = 128; off > 0; off >>= 1) {
        if (tid < off) {
            s0[tid] += s0[tid + off];
            s1[tid] += s1[tid + off];
        }
        __syncthreads();
    }
    if (tid == 0) {
        out[b * 2 + 0] = s0[0] + blin[0];
        out[b * 2 + 1] = s1[0] + blin[1];
    }
}

// ---------------------------------------------------------------------------
extern "C" void kernel_launch(void* const* d_in, const int* in_sizes, int n_in,
                              void* d_out, int out_size) {
    const float* x      = (const float*)d_in[0];
    const float* W_ih_f = (const float*)d_in[1];
    const float* W_hh_f = (const float*)d_in[2];
    const float* b_f    = (const float*)d_in[3];
    const float* W_ih_b = (const float*)d_in[4];
    // d_in[5] = W_hh_b : provably unused (backward dir needs only its first step, h0=0)
    const float* b_b    = (const float*)d_in[6];
    const float* W_lin  = (const float*)d_in[7];
    const float* b_lin  = (const float*)d_in[8];
    float* out = (float*)d_out;

    init_state<<<(BB * HH + 255) / 256, 256>>>();
    xp_gemm<<<dim3(8, 512), 256>>>(x, W_ih_f, b_f);
    bwd_last<<<BB, 256>>>(x, W_ih_b, b_b);

    for (int t = 0; t < TT; t++) {
        lstm_step<<<dim3(32, 4), 256>>>(W_hh_f, t, t & 1);
    }

    final_lin<<<BB, 256>>>(W_lin, b_lin, out);
}

// round 3
// speedup vs baseline: 1.2266x; 1.2266x over previous
#include <cuda_runtime.h>
#include <math.h>
#include <stdint.h>

// Problem dims
#define BB 128
#define TT 512
#define II 300
#define HH 256
#define G4 1024   // 4*H
#define NCTA 128
#define HPAD 260  // padded row stride (floats) for smem tiles

// Scratch (device globals — no allocations allowed)
__device__ float g_xp[(size_t)TT * BB * G4];   // [t][b][gate]  (256 MB)
__device__ float g_h[2][BB * HH];              // ping-pong hidden state
__device__ float g_hb[BB * HH];                // backward-dir last hidden
__device__ unsigned g_bar;                     // grid barrier counter

__device__ __forceinline__ float sigmoidf(float v) {
    return 1.0f / (1.0f + expf(-v));
}

// ---------------------------------------------------------------------------
// Init: zero h[0] and the barrier counter (every launch/replay).
// ---------------------------------------------------------------------------
__global__ void init_state() {
    int i = blockIdx.x * blockDim.x + threadIdx.x;
    if (i < BB * HH) g_h[0][i] = 0.0f;
    if (i == 0) g_bar = 0u;
}

// ---------------------------------------------------------------------------
// xp GEMM: xp[t][b][n] = sum_i x[b][t][i] * W_ih_f[n][i] + b_f[n]
// Tile 128x128, Ktile 8, 256 threads, 8x8 micro-tile.
// ---------------------------------------------------------------------------
__global__ void xp_gemm(const float* __restrict__ A,
                        const float* __restrict__ W,
                        const float* __restrict__ bias) {
    __shared__ float As[8][132];
    __shared__ float Bs[8][132];

    const int nt = blockIdx.x;          // 0..7
    const int mt = blockIdx.y;          // 0..511
    const int tid = threadIdx.x;        // 0..255
    const int tx = tid & 15;
    const int ty = tid >> 4;

    const int m0 = mt * 128;
    const int n0 = nt * 128;

    float acc[8][8];
#pragma unroll
    for (int i = 0; i < 8; i++)
#pragma unroll
        for (int j = 0; j < 8; j++) acc[i][j] = 0.0f;

    for (int k0 = 0; k0 < II; k0 += 8) {
#pragma unroll
        for (int e = tid; e < 1024; e += 256) {
            int r = e >> 3;
            int kk = e & 7;
            int k = k0 + kk;
            As[kk][r] = (k < II) ? A[(size_t)(m0 + r) * II + k] : 0.0f;
            Bs[kk][r] = (k < II) ? W[(size_t)(n0 + r) * II + k] : 0.0f;
        }
        __syncthreads();

#pragma unroll
        for (int kk = 0; kk < 8; kk++) {
            float a[8], b[8];
#pragma unroll
            for (int i = 0; i < 8; i++) a[i] = As[kk][ty * 8 + i];
#pragma unroll
            for (int j = 0; j < 8; j++) b[j] = Bs[kk][tx * 8 + j];
#pragma unroll
            for (int i = 0; i < 8; i++)
#pragma unroll
                for (int j = 0; j < 8; j++) acc[i][j] += a[i] * b[j];
        }
        __syncthreads();
    }

#pragma unroll
    for (int i = 0; i < 8; i++) {
        int m = m0 + ty * 8 + i;
        int bidx = m >> 9;      // m / 512
        int t = m & 511;        // m % 512
        size_t base = ((size_t)t * BB + bidx) * G4;
#pragma unroll
        for (int j = 0; j < 8; j++) {
            int n = n0 + tx * 8 + j;
            g_xp[base + n] = acc[i][j] + bias[n];
        }
    }
}

// ---------------------------------------------------------------------------
// Backward direction: only ONE step matters (h0=c0=0 on x[:, T-1]).
// ---------------------------------------------------------------------------
__global__ void bwd_last(const float* __restrict__ x,
                         const float* __restrict__ Wb,
                         const float* __restrict__ bb) {
    const int b = blockIdx.x;
    const int tid = threadIdx.x;        // 256
    __shared__ float xs[304];
    __shared__ float gs[G4];

    const float* xr = x + ((size_t)b * TT + (TT - 1)) * II;
    for (int i = tid; i < II; i += 256) xs[i] = xr[i];
    __syncthreads();

    const int wid = tid >> 5;
    const int lane = tid & 31;
    for (int r = wid; r < G4; r += 8) {
        float s = 0.0f;
        const float* wr = Wb + (size_t)r * II;
        for (int i = lane; i < II; i += 32) s += xs[i] * wr[i];
#pragma unroll
        for (int off = 16; off > 0; off >>= 1)
            s += __shfl_down_sync(0xffffffffu, s, off);
        if (lane == 0) gs[r] = s + bb[r];
    }
    __syncthreads();

    if (tid < HH) {
        float ig = sigmoidf(gs[tid]);
        float gg = tanhf(gs[512 + tid]);
        float og = sigmoidf(gs[768 + tid]);
        float c = ig * gg;               // f * c0 = 0
        g_hb[b * HH + tid] = og * tanhf(c);
    }
}

// ---------------------------------------------------------------------------
// Persistent forward recurrence. One launch for all 512 steps.
// Grid: 128 CTAs (bt = blockIdx/32 -> 32 batches, gt = blockIdx%32 -> 8
// hidden units x 4 gates = 32 W rows). 512 threads:
//   compute role: (ks = tid>>8) halves K; 2x2 micro-tile (ty/ty+16 batches,
//                 tx/tx+16 rows); partials to smem.
//   gate role (tid<256): (gb = tid>>3 batch, gu = tid&7 hidden unit); owns
//                 the cell state c in a register for the whole sequence.
// W_hh tile lives in smem for all 512 steps. h ping-pongs through global
// (ldcg/stcg: L1 incoherent inside a persistent kernel). Grid barrier =
// monotonic atomic counter + acquire spin. All 128 CTAs are co-resident
// (75KB smem/CTA, 1-2 CTAs per SM possible, 128 <= 148 SMs): no deadlock.
// ---------------------------------------------------------------------------
__global__ void __launch_bounds__(512, 1) lstm_persist(const float* __restrict__ Whh) {
    extern __shared__ float sm[];
    float* W_s = sm;                 // [32][HPAD]
    float* h_s = sm + 32 * HPAD;     // [32][HPAD]
    float* ps  = sm + 64 * HPAD;     // [2*32][33] partial sums

    const int tid = threadIdx.x;
    const int bt = blockIdx.x >> 5;   // 0..3
    const int gt = blockIdx.x & 31;   // 0..31

    // ---- load W tile once (rows lr = gate*8 + unit) ----
    for (int idx = tid; idx < 32 * 64; idx += 512) {
        int lr = idx >> 6;
        int kc = (idx & 63) * 4;
        int grow = (lr >> 3) * HH + gt * 8 + (lr & 7);
        float4 v = *(const float4*)&Whh[(size_t)grow * HH + kc];
        *(float4*)&W_s[lr * HPAD + kc] = v;
    }

    // role constants
    const int gb = tid >> 3;            // gate role: local batch (tid<256)
    const int gu = tid & 7;             // gate role: hidden unit
    const int ks = tid >> 8;            // compute role: K half
    const int tx = tid & 15;
    const int ty = (tid >> 4) & 15;
    float c_reg = 0.0f;                 // cell state, register-resident

    __syncthreads();

    for (int t = 0; t < TT; t++) {
        const float* __restrict__ h_in = g_h[t & 1];
        float* __restrict__ h_out = g_h[(t + 1) & 1];

        // prefetch this step's xp into registers (overlaps compute)
        float xi = 0.f, xf = 0.f, xg = 0.f, xo = 0.f;
        if (tid < 256) {
            size_t xb = ((size_t)t * BB + bt * 32 + gb) * G4 + gt * 8 + gu;
            xi = __ldg(&g_xp[xb]);
            xf = __ldg(&g_xp[xb + 256]);
            xg = __ldg(&g_xp[xb + 512]);
            xo = __ldg(&g_xp[xb + 768]);
        }

        // stage h tile (L1-bypassing loads: data written by other SMs)
        for (int idx = tid; idx < 32 * 64; idx += 512) {
            int lb = idx >> 6;
            int kc = (idx & 63) * 4;
            float4 v = __ldcg((const float4*)&h_in[(size_t)(bt * 32 + lb) * HH + kc]);
            *(float4*)&h_s[lb * HPAD + kc] = v;
        }
        __syncthreads();

        // compute: 2x2 micro-tile over this thread's K half
        float a00 = 0.f, a01 = 0.f, a10 = 0.f, a11 = 0.f;
        {
            const float* hp0 = &h_s[ty * HPAD + ks * 128];
            const float* hp1 = hp0 + 16 * HPAD;
            const float* wp0 = &W_s[tx * HPAD + ks * 128];
            const float* wp1 = wp0 + 16 * HPAD;
#pragma unroll
            for (int k = 0; k < 128; k += 4) {
                float4 h0 = *(const float4*)(hp0 + k);
                float4 h1 = *(const float4*)(hp1 + k);
                float4 w0 = *(const float4*)(wp0 + k);
                float4 w1 = *(const float4*)(wp1 + k);
                a00 += h0.x * w0.x + h0.y * w0.y + h0.z * w0.z + h0.w * w0.w;
                a01 += h0.x * w1.x + h0.y * w1.y + h0.z * w1.z + h0.w * w1.w;
                a10 += h1.x * w0.x + h1.y * w0.y + h1.z * w0.z + h1.w * w0.w;
                a11 += h1.x * w1.x + h1.y * w1.y + h1.z * w1.z + h1.w * w1.w;
            }
        }
        {
            int base0 = (ks * 32 + ty) * 33;
            int base1 = (ks * 32 + ty + 16) * 33;
            ps[base0 + tx] = a00;
            ps[base0 + tx + 16] = a01;
            ps[base1 + tx] = a10;
            ps[base1 + tx + 16] = a11;
        }
        __syncthreads();

        // gates: reduce K halves, add xp, update c (register), emit h
        if (tid < 256) {
            const float* p0 = &ps[gb * 33];
            const float* p1 = &ps[(32 + gb) * 33];
            float pi = p0[gu]      + p1[gu]      + xi;
            float pf = p0[8 + gu]  + p1[8 + gu]  + xf;
            float pg = p0[16 + gu] + p1[16 + gu] + xg;
            float po = p0[24 + gu] + p1[24 + gu] + xo;
            float ig = sigmoidf(pi);
            float fg = sigmoidf(pf);
            float gg = tanhf(pg);
            float og = sigmoidf(po);
            c_reg = fg * c_reg + ig * gg;
            float h = og * tanhf(c_reg);
            __stcg(&h_out[(size_t)(bt * 32 + gb) * HH + gt * 8 + gu], h);
            __threadfence();   // make h visible device-wide before arrival
        }
        __syncthreads();

        // grid-wide barrier (monotonic counter, acquire spin)
        if (tid == 0) {
            atomicAdd(&g_bar, 1u);
            unsigned tgt = (unsigned)(t + 1) * NCTA;
            unsigned v;
            do {
                asm volatile("ld.global.acquire.gpu.u32 %0, [%1];"
                             : "=r"(v) : "l"(&g_bar));
                if (v < tgt) __nanosleep(64);
            } while (v < tgt);
        }
        __syncthreads();
    }
}

// ---------------------------------------------------------------------------
// Final linear. hf lives in g_h[0] after 512 steps.
// ---------------------------------------------------------------------------
__global__ void final_lin(const float* __restrict__ Wlin,
                          const float* __restrict__ blin,
                          float* __restrict__ out) {
    const int b = blockIdx.x;
    const int tid = threadIdx.x;  // 256
    __shared__ float s0[256];
    __shared__ float s1[256];

    float hf = g_h[0][b * HH + tid];
    float hb = g_hb[b * HH + tid];
    s0[tid] = hf * Wlin[tid] + hb * Wlin[HH + tid];
    s1[tid] = hf * Wlin[512 + tid] + hb * Wlin[512 + HH + tid];
    __syncthreads();
    for (int off = 128; off > 0; off >>= 1) {
        if (tid < off) {
            s0[tid] += s0[tid + off];
            s1[tid] += s1[tid + off];
        }
        __syncthreads();
    }
    if (tid == 0) {
        out[b * 2 + 0] = s0[0] + blin[0];
        out[b * 2 + 1] = s1[0] + blin[1];
    }
}

// ---------------------------------------------------------------------------
extern "C" void kernel_launch(void* const* d_in, const int* in_sizes, int n_in,
                              void* d_out, int out_size) {
    const float* x      = (const float*)d_in[0];
    const float* W_ih_f = (const float*)d_in[1];
    const float* W_hh_f = (const float*)d_in[2];
    const float* b_f    = (const float*)d_in[3];
    const float* W_ih_b = (const float*)d_in[4];
    // d_in[5] = W_hh_b : unused (backward dir needs only its first step, h0=0)
    const float* b_b    = (const float*)d_in[6];
    const float* W_lin  = (const float*)d_in[7];
    const float* b_lin  = (const float*)d_in[8];
    float* out = (float*)d_out;

    const int smem_bytes = (64 * HPAD + 2 * 32 * 33) * 4;  // 75008
    cudaFuncSetAttribute(lstm_persist,
                         cudaFuncAttributeMaxDynamicSharedMemorySize, smem_bytes);

    init_state<<<(BB * HH + 255) / 256, 256>>>();
    xp_gemm<<<dim3(8, 512), 256>>>(x, W_ih_f, b_f);
    bwd_last<<<BB, 256>>>(x, W_ih_b, b_b);
    lstm_persist<<<NCTA, 512, smem_bytes>>>(W_hh_f);
    final_lin<<<BB, 256>>>(W_lin, b_lin, out);
}

// round 4
// speedup vs baseline: 1.3471x; 1.0982x over previous
#include <cuda_runtime.h>
#include <math.h>
#include <stdint.h>

// Problem dims
#define BB 128
#define TT 512
#define II 300
#define HH 256
#define G4 1024   // 4*H

// persist kernel geometry
#define CL 8         // CTAs per cluster
#define NCLUS 16     // clusters (NCLUS*CL = 128 CTAs)
#define PW 260       // W_s row pad (floats)
#define PH 260       // h row pad (floats)
#define PSB 9        // partial-sum batch pad

// Scratch (device globals — no allocations allowed)
__device__ float g_xp[(size_t)TT * BB * G4];   // [t][b][gate]  (256 MB)
__device__ float g_hf[BB * HH];                // forward-dir final hidden
__device__ float g_hb[BB * HH];                // backward-dir final hidden

__device__ __forceinline__ float fast_sigmoid(float v) {
    return 1.0f / (1.0f + __expf(-v));
}
__device__ __forceinline__ float fast_tanh(float v) {
    // 2/(1+e^{-2v}) - 1 ; __expf rel err ~2^-21, safe at 1e-3 tolerance
    return __fdividef(2.0f, 1.0f + __expf(-2.0f * v)) - 1.0f;
}

// packed dual-fp32 FMA (sm_103a runs FFMA at rt=2/SMSP; f32x2 doubles throughput)
__device__ __forceinline__ void fma2(float2& acc, float2 a, float2 b) {
    asm("fma.rn.f32x2 %0, %1, %2, %0;"
        : "+l"(reinterpret_cast<unsigned long long&>(acc))
        : "l"(reinterpret_cast<unsigned long long&>(a)),
          "l"(reinterpret_cast<unsigned long long&>(b)));
}

__device__ __forceinline__ void st_remote_f32(uint32_t saddr, uint32_t trank, float v) {
    uint32_t ra;
    asm volatile("mapa.shared::cluster.u32 %0, %1, %2;" : "=r"(ra) : "r"(saddr), "r"(trank));
    asm volatile("st.shared::cluster.f32 [%0], %1;" :: "r"(ra), "f"(v) : "memory");
}

// ---------------------------------------------------------------------------
// xp GEMM: xp[t][b][n] = sum_i x[b][t][i] * W_ih_f[n][i] + b_f[n]
// Tile 128x128, Ktile 8, 256 threads, 8x8 micro-tile, f32x2 inner product.
// ---------------------------------------------------------------------------
__global__ void xp_gemm(const float* __restrict__ A,
                        const float* __restrict__ W,
                        const float* __restrict__ bias) {
    __shared__ float As[8][132];
    __shared__ float Bs[8][132];

    const int nt = blockIdx.x;          // 0..7
    const int mt = blockIdx.y;          // 0..511
    const int tid = threadIdx.x;        // 0..255
    const int tx = tid & 15;
    const int ty = tid >> 4;

    const int m0 = mt * 128;
    const int n0 = nt * 128;

    float2 acc2[4][8];                  // i-pairs (m dim) x j (n dim)
#pragma unroll
    for (int ip = 0; ip < 4; ip++)
#pragma unroll
        for (int j = 0; j < 8; j++) acc2[ip][j] = make_float2(0.f, 0.f);

    for (int k0 = 0; k0 < II; k0 += 8) {
#pragma unroll
        for (int e = tid; e < 1024; e += 256) {
            int r = e >> 3;
            int kk = e & 7;
            int k = k0 + kk;
            As[kk][r] = (k < II) ? A[(size_t)(m0 + r) * II + k] : 0.0f;
            Bs[kk][r] = (k < II) ? W[(size_t)(n0 + r) * II + k] : 0.0f;
        }
        __syncthreads();

#pragma unroll
        for (int kk = 0; kk < 8; kk++) {
            float4 a0 = *(const float4*)&As[kk][ty * 8];
            float4 a1 = *(const float4*)&As[kk][ty * 8 + 4];
            float4 b0 = *(const float4*)&Bs[kk][tx * 8];
            float4 b1 = *(const float4*)&Bs[kk][tx * 8 + 4];
            float2 ap[4] = { {a0.x, a0.y}, {a0.z, a0.w}, {a1.x, a1.y}, {a1.z, a1.w} };
            float bj[8] = { b0.x, b0.y, b0.z, b0.w, b1.x, b1.y, b1.z, b1.w };
#pragma unroll
            for (int j = 0; j < 8; j++) {
                float2 bb = make_float2(bj[j], bj[j]);
#pragma unroll
                for (int ip = 0; ip < 4; ip++) fma2(acc2[ip][j], ap[ip], bb);
            }
        }
        __syncthreads();
    }

#pragma unroll
    for (int i = 0; i < 8; i++) {
        int m = m0 + ty * 8 + i;
        int bidx = m >> 9;      // m / 512
        int t = m & 511;        // m % 512
        size_t base = ((size_t)t * BB + bidx) * G4;
#pragma unroll
        for (int j = 0; j < 8; j++) {
            int n = n0 + tx * 8 + j;
            float v = (i & 1) ? acc2[i >> 1][j].y : acc2[i >> 1][j].x;
            g_xp[base + n] = v + bias[n];
        }
    }
}

// ---------------------------------------------------------------------------
// Backward direction: only ONE step matters (h0=c0=0 on x[:, T-1]).
// ---------------------------------------------------------------------------
__global__ void bwd_last(const float* __restrict__ x,
                         const float* __restrict__ Wb,
                         const float* __restrict__ bb) {
    const int b = blockIdx.x;
    const int tid = threadIdx.x;        // 256
    __shared__ float xs[304];
    __shared__ float gs[G4];

    const float* xr = x + ((size_t)b * TT + (TT - 1)) * II;
    for (int i = tid; i < II; i += 256) xs[i] = xr[i];
    __syncthreads();

    const int wid = tid >> 5;
    const int lane = tid & 31;
    for (int r = wid; r < G4; r += 8) {
        float s = 0.0f;
        const float* wr = Wb + (size_t)r * II;
        for (int i = lane; i < II; i += 32) s += xs[i] * wr[i];
#pragma unroll
        for (int off = 16; off > 0; off >>= 1)
            s += __shfl_down_sync(0xffffffffu, s, off);
        if (lane == 0) gs[r] = s + bb[r];
    }
    __syncthreads();

    if (tid < HH) {
        float ig = 1.0f / (1.0f + expf(-gs[tid]));
        float gg = tanhf(gs[512 + tid]);
        float og = 1.0f / (1.0f + expf(-gs[768 + tid]));
        float c = ig * gg;               // f * c0 = 0
        g_hb[b * HH + tid] = og * tanhf(c);
    }
}

// ---------------------------------------------------------------------------
// Persistent forward recurrence, cluster version. 16 clusters x 8 CTAs.
// Cluster = 8 batches (independent of all other clusters -> no global sync).
// CTA rank r holds W rows {g*256 + r*32 + u : g<4, u<32} in smem forever.
// h[8][256] lives in every CTA's smem (double buffered); after gates each
// CTA scatters its 32-unit slice to all 8 cluster CTAs via DSMEM, then one
// cluster.sync. Cell state c is register-resident in the gate threads.
// Threads (512): mainloop role (ks = tid>>6 k-chunk, rr = tid&63 -> W rows
// rr and rr+64; 8 batches each; f32x2 FMAs). Gate role: tid<256,
// gb = tid>>5 batch, gu = tid&31 hidden unit.
// ---------------------------------------------------------------------------
__global__ void __launch_bounds__(512, 1) __cluster_dims__(CL, 1, 1)
lstm_persist(const float* __restrict__ Whh) {
    extern __shared__ float sm[];
    float* W_s = sm;                        // [128][PW]
    float* h_s = sm + 128 * PW;             // [2][8][PH]
    float* ps  = h_s + 2 * 8 * PH;          // [8*128*PSB]

    const int tid = threadIdx.x;
    uint32_t rank;
    asm("mov.u32 %0, %%cluster_ctarank;" : "=r"(rank));
    const int cid = blockIdx.x >> 3;

    // ---- load W slice once: local row lr -> global row (lr>>5)*256 + rank*32 + (lr&31)
    for (int idx = tid; idx < 128 * 64; idx += 512) {
        int lr = idx >> 6;
        int k4 = (idx & 63) * 4;
        int grow = (lr >> 5) * HH + (int)rank * 32 + (lr & 31);
        float4 v = *(const float4*)&Whh[(size_t)grow * HH + k4];
        *(float4*)&W_s[lr * PW + k4] = v;
    }
    // zero h buffer 0 only (buffer 1 is fully written by the first exchange)
    for (int i = tid; i < 8 * PH; i += 512) h_s[i] = 0.0f;
    __syncthreads();

    const int rr = tid & 63;
    const int ks = tid >> 6;
    const int gb = tid >> 5;            // gate role (tid<256)
    const int gu = tid & 31;
    const int bglob = cid * CL + gb;
    float c_reg = 0.0f;
    float h_last = 0.0f;

    const uint32_t h_sh_base = (uint32_t)__cvta_generic_to_shared(h_s);

    for (int t = 0; t < TT; t++) {
        const int cur = t & 1;
        const float* __restrict__ hcur = h_s + cur * 8 * PH;

        // prefetch xp for this step (consumed after mainloop -> latency hidden)
        float xi = 0.f, xf = 0.f, xg = 0.f, xo = 0.f;
        if (tid < 256) {
            size_t xb = ((size_t)t * BB + bglob) * G4 + rank * 32 + gu;
            xi = __ldg(&g_xp[xb]);
            xf = __ldg(&g_xp[xb + 256]);
            xg = __ldg(&g_xp[xb + 512]);
            xo = __ldg(&g_xp[xb + 768]);
        }

        // mainloop: rows rr, rr+64 x 8 batches, K chunk [ks*32, ks*32+32)
        float2 acc2[2][8];
#pragma unroll
        for (int r = 0; r < 2; r++)
#pragma unroll
            for (int b = 0; b < 8; b++) acc2[r][b] = make_float2(0.f, 0.f);

        const float* wp0 = &W_s[rr * PW + ks * 32];
        const float* wp1 = &W_s[(rr + 64) * PW + ks * 32];
        const float* hp = hcur + ks * 32;
#pragma unroll
        for (int kk = 0; kk < 8; kk++) {
            float4 w0 = *(const float4*)(wp0 + kk * 4);
            float4 w1 = *(const float4*)(wp1 + kk * 4);
            float2 w0l = make_float2(w0.x, w0.y), w0h = make_float2(w0.z, w0.w);
            float2 w1l = make_float2(w1.x, w1.y), w1h = make_float2(w1.z, w1.w);
#pragma unroll
            for (int b = 0; b < 8; b++) {
                float4 h4 = *(const float4*)(hp + b * PH + kk * 4);
                float2 hl = make_float2(h4.x, h4.y), hh = make_float2(h4.z, h4.w);
                fma2(acc2[0][b], w0l, hl);
                fma2(acc2[0][b], w0h, hh);
                fma2(acc2[1][b], w1l, hl);
                fma2(acc2[1][b], w1h, hh);
            }
        }
        // partials: ps[(ks*128 + lr)*PSB + b]
#pragma unroll
        for (int b = 0; b < 8; b++) {
            ps[(ks * 128 + rr) * PSB + b]      = acc2[0][b].x + acc2[0][b].y;
            ps[(ks * 128 + rr + 64) * PSB + b] = acc2[1][b].x + acc2[1][b].y;
        }
        __syncthreads();

        // gates: reduce over 8 k-chunks, add xp, update c, scatter h to cluster
        if (tid < 256) {
            float pi = xi, pf = xf, pg = xg, po = xo;
#pragma unroll
            for (int s = 0; s < 8; s++) {
                int base = s * 128 * PSB;
                pi += ps[base + (gu) * PSB + gb];
                pf += ps[base + (32 + gu) * PSB + gb];
                pg += ps[base + (64 + gu) * PSB + gb];
                po += ps[base + (96 + gu) * PSB + gb];
            }
            float ig = fast_sigmoid(pi);
            float fg = fast_sigmoid(pf);
            float gg = fast_tanh(pg);
            float og = fast_sigmoid(po);
            c_reg = fg * c_reg + ig * gg;
            float h = og * fast_tanh(c_reg);
            h_last = h;
            // write into every cluster CTA's h_s[nxt][gb][rank*32+gu]
            uint32_t off = h_sh_base +
                (uint32_t)(((cur ^ 1) * 8 * PH + gb * PH + (int)rank * 32 + gu) * 4);
#pragma unroll
            for (int r = 0; r < CL; r++) st_remote_f32(off, (uint32_t)r, h);
        }
        // cluster barrier: orders DSMEM writes (arrive=release, wait=acquire)
        asm volatile("barrier.cluster.arrive.aligned;" ::: "memory");
        asm volatile("barrier.cluster.wait.aligned;" ::: "memory");
    }

    if (tid < 256) {
        g_hf[bglob * HH + (int)rank * 32 + gu] = h_last;
    }
}

// ---------------------------------------------------------------------------
// Final linear: out[b][j] = b_lin[j] + hf[b]·W_lin[j,:256] + hb[b]·W_lin[j,256:]
// ---------------------------------------------------------------------------
__global__ void final_lin(const float* __restrict__ Wlin,
                          const float* __restrict__ blin,
                          float* __restrict__ out) {
    const int b = blockIdx.x;
    const int tid = threadIdx.x;  // 256
    __shared__ float s0[256];
    __shared__ float s1[256];

    float hf = g_hf[b * HH + tid];
    float hb = g_hb[b * HH + tid];
    s0[tid] = hf * Wlin[tid] + hb * Wlin[HH + tid];
    s1[tid] = hf * Wlin[512 + tid] + hb * Wlin[512 + HH + tid];
    __syncthreads();
    for (int off = 128; off > 0; off >>= 1) {
        if (tid < off) {
            s0[tid] += s0[tid + off];
            s1[tid] += s1[tid + off];
        }
        __syncthreads();
    }
    if (tid == 0) {
        out[b * 2 + 0] = s0[0] + blin[0];
        out[b * 2 + 1] = s1[0] + blin[1];
    }
}

// ---------------------------------------------------------------------------
extern "C" void kernel_launch(void* const* d_in, const int* in_sizes, int n_in,
                              void* d_out, int out_size) {
    const float* x      = (const float*)d_in[0];
    const float* W_ih_f = (const float*)d_in[1];
    const float* W_hh_f = (const float*)d_in[2];
    const float* b_f    = (const float*)d_in[3];
    const float* W_ih_b = (const float*)d_in[4];
    // d_in[5] = W_hh_b : unused (backward dir needs only its first step, h0=0)
    const float* b_b    = (const float*)d_in[6];
    const float* W_lin  = (const float*)d_in[7];
    const float* b_lin  = (const float*)d_in[8];
    float* out = (float*)d_out;

    const int smem_bytes = (128 * PW + 2 * 8 * PH + 8 * 128 * PSB) * 4; // 186624
    cudaFuncSetAttribute(lstm_persist,
                         cudaFuncAttributeMaxDynamicSharedMemorySize, smem_bytes);

    xp_gemm<<<dim3(8, 512), 256>>>(x, W_ih_f, b_f);
    bwd_last<<<BB, 256>>>(x, W_ih_b, b_b);
    lstm_persist<<<NCLUS * CL, 512, smem_bytes>>>(W_hh_f);
    final_lin<<<BB, 256>>>(W_lin, b_lin, out);
}